// round 2
// baseline (speedup 1.0000x reference)
#include <cuda_runtime.h>
#include <math.h>

#define NH 64      // B*H
#define NN 4096
#define DD 64
#define MM 256

#define SCALE 0.35355339059327379f   // 64^-0.25
#define RATIO 0.0625f                // 256^-0.5
#define EPSILON 1e-4f

// ---- scratch (__device__ globals: allocation-free per harness rules) ----
__device__ float    g_kdash[(size_t)NH * NN * MM];   // 268 MB
__device__ float    g_qp   [(size_t)NH * NN * MM];   // 268 MB
__device__ float    g_kdiag[NH * NN];
__device__ float    g_ctx  [NH * MM * DD];
__device__ float    g_ksum [NH * MM];
__device__ unsigned g_gmax [NH];

__device__ __forceinline__ unsigned enc_f(float f) {
    unsigned u = __float_as_uint(f);
    return (u & 0x80000000u) ? ~u : (u | 0x80000000u);
}
__device__ __forceinline__ float dec_f(unsigned u) {
    return __uint_as_float((u & 0x80000000u) ? (u & 0x7fffffffu) : ~u);
}

// ---------------------------------------------------------------- K0: init
__global__ void k0_init() {
    int i = blockIdx.x * blockDim.x + threadIdx.x;
    if (i < NH * MM * DD) g_ctx[i] = 0.0f;
    if (i < NH * MM)      g_ksum[i] = 0.0f;
    if (i < NH)           g_gmax[i] = 0u;
}

// --------------------------------------------- K1: kdash = (s*k)·projT, gmax, kdiag
__global__ void __launch_bounds__(256) k1_kproj(const float* __restrict__ K,
                                                const float* __restrict__ P) {
    int head = blockIdx.z;
    int n0 = blockIdx.x * 64;
    int m0 = blockIdx.y * 64;
    __shared__ float ks[64][65];
    __shared__ float ps[64][65];
    __shared__ float red[256];
    int tid = threadIdx.x;
    const float* kb = K + (size_t)head * NN * DD;
    for (int i = tid; i < 64 * 64; i += 256) {
        int r = i >> 6, c = i & 63;
        ks[r][c] = SCALE * kb[(size_t)(n0 + r) * DD + c];
        ps[r][c] = P[(size_t)(m0 + r) * DD + c];
    }
    __syncthreads();
    int tx = tid & 15, ty = tid >> 4;
    float acc[4][4] = {};
    #pragma unroll 8
    for (int d = 0; d < 64; d++) {
        float a[4], b[4];
        #pragma unroll
        for (int i = 0; i < 4; i++) a[i] = ks[ty + 16 * i][d];
        #pragma unroll
        for (int j = 0; j < 4; j++) b[j] = ps[tx + 16 * j][d];
        #pragma unroll
        for (int i = 0; i < 4; i++)
            #pragma unroll
            for (int j = 0; j < 4; j++) acc[i][j] += a[i] * b[j];
    }
    float lmax = -1e30f;
    float* outp = g_kdash + ((size_t)head * NN + n0) * MM + m0;
    #pragma unroll
    for (int i = 0; i < 4; i++)
        #pragma unroll
        for (int j = 0; j < 4; j++) {
            float v = acc[i][j];
            lmax = fmaxf(lmax, v);
            outp[(size_t)(ty + 16 * i) * MM + (tx + 16 * j)] = v;
        }
    red[tid] = lmax;
    __syncthreads();
    for (int s = 128; s > 0; s >>= 1) {
        if (tid < s) red[tid] = fmaxf(red[tid], red[tid + s]);
        __syncthreads();
    }
    if (tid == 0) atomicMax(&g_gmax[head], enc_f(red[0]));
    if (blockIdx.y == 0 && tid < 64) {
        float s = 0.0f;
        #pragma unroll 8
        for (int d = 0; d < 64; d++) s += ks[tid][d] * ks[tid][d];
        g_kdiag[head * NN + n0 + tid] = 0.5f * s;
    }
}

// --------------------------------------------- K2: qp = ratio*(exp(qdash - diag - rowmax)+eps)
// dyn smem: qs[32*65] ps[64*65] dash[32*256] diag[32] mxs[32] pmax[32*8]
#define K2_SMEM ((32 * 65 + 64 * 65 + 32 * 256 + 32 + 32 + 256) * 4)
__global__ void __launch_bounds__(256) k2_qp(const float* __restrict__ Q,
                                             const float* __restrict__ P) {
    extern __shared__ float sm[];
    float* qs   = sm;
    float* ps   = qs + 32 * 65;
    float* dash = ps + 64 * 65;
    float* diag = dash + 32 * 256;
    float* mxs  = diag + 32;
    float* pmax = mxs + 32;

    int head = blockIdx.y;
    int n0 = blockIdx.x * 32;
    int tid = threadIdx.x;
    const float* qb = Q + (size_t)head * NN * DD;
    for (int i = tid; i < 32 * 64; i += 256) {
        int r = i >> 6, c = i & 63;
        qs[r * 65 + c] = SCALE * qb[(size_t)(n0 + r) * DD + c];
    }
    __syncthreads();
    if (tid < 32) {
        float s = 0.0f;
        #pragma unroll 8
        for (int d = 0; d < 64; d++) { float v = qs[tid * 65 + d]; s += v * v; }
        diag[tid] = 0.5f * s;
    }
    int tx = tid & 15, ty = tid >> 4;
    for (int mc = 0; mc < 4; mc++) {
        int m0 = mc * 64;
        __syncthreads();
        for (int i = tid; i < 64 * 64; i += 256) {
            int r = i >> 6, c = i & 63;
            ps[r * 65 + c] = P[(size_t)(m0 + r) * DD + c];
        }
        __syncthreads();
        float acc[2][4] = {};
        #pragma unroll 8
        for (int d = 0; d < 64; d++) {
            float a0 = qs[ty * 65 + d], a1 = qs[(ty + 16) * 65 + d];
            float b[4];
            #pragma unroll
            for (int j = 0; j < 4; j++) b[j] = ps[(tx + 16 * j) * 65 + d];
            #pragma unroll
            for (int j = 0; j < 4; j++) { acc[0][j] += a0 * b[j]; acc[1][j] += a1 * b[j]; }
        }
        #pragma unroll
        for (int i = 0; i < 2; i++)
            #pragma unroll
            for (int j = 0; j < 4; j++)
                dash[(ty + 16 * i) * 256 + m0 + tx + 16 * j] = acc[i][j];
    }
    __syncthreads();
    {   // row max
        int r = tid >> 3, seg = tid & 7;
        float m = -1e30f;
        for (int mm = seg * 32; mm < seg * 32 + 32; mm++) m = fmaxf(m, dash[r * 256 + mm]);
        pmax[r * 8 + seg] = m;
    }
    __syncthreads();
    if (tid < 32) {
        float m = -1e30f;
        #pragma unroll
        for (int s = 0; s < 8; s++) m = fmaxf(m, pmax[tid * 8 + s]);
        mxs[tid] = m;
    }
    __syncthreads();
    // tid = feature index m (0..255); write all 32 rows, coalesced
    for (int r = 0; r < 32; r++) {
        float v = RATIO * (expf(dash[r * 256 + tid] - diag[r] - mxs[r]) + EPSILON);
        g_qp[((size_t)head * NN + n0 + r) * MM + tid] = v;
    }
}

// --------------------------------------------- K3: context[m,e] += kp[n,m]*v[n,e]; ksum[m] += kp
__global__ void __launch_bounds__(256) k3_ctx(const float* __restrict__ V) {
    __shared__ float kps[16 * 256];
    __shared__ float vs[16 * 64];
    __shared__ float kdg[16];
    int head = blockIdx.y;
    int n_base = blockIdx.x * 256;
    int tid = threadIdx.x;
    float gmx = dec_f(g_gmax[head]);
    int t_e = tid & 7;
    int t_m = tid >> 3;
    float cacc[8][8] = {};
    float ksacc[8] = {};
    const float* vb = V + (size_t)head * NN * DD;
    for (int ch = 0; ch < 16; ch++) {
        int n0 = n_base + ch * 16;
        __syncthreads();
        if (tid < 16) kdg[tid] = g_kdiag[head * NN + n0 + tid];
        for (int i = tid; i < 16 * 64; i += 256) {
            int r = i >> 6, c = i & 63;
            vs[r * 64 + c] = vb[(size_t)(n0 + r) * 64 + c];
        }
        __syncthreads();
        #pragma unroll
        for (int r = 0; r < 16; r++) {
            float d0 = g_kdash[((size_t)head * NN + n0 + r) * MM + tid];
            kps[r * 256 + tid] = RATIO * (expf(d0 - kdg[r] - gmx) + EPSILON);
        }
        __syncthreads();
        #pragma unroll
        for (int nn = 0; nn < 16; nn++) {
            float a[8], b[8];
            #pragma unroll
            for (int i = 0; i < 8; i++) a[i] = kps[nn * 256 + t_m + 32 * i];
            #pragma unroll
            for (int j = 0; j < 8; j++) b[j] = vs[nn * 64 + t_e + 8 * j];
            #pragma unroll
            for (int i = 0; i < 8; i++)
                #pragma unroll
                for (int j = 0; j < 8; j++) cacc[i][j] += a[i] * b[j];
            if (t_e == 0) {
                #pragma unroll
                for (int i = 0; i < 8; i++) ksacc[i] += a[i];
            }
        }
    }
    float* ctx = g_ctx + (size_t)head * MM * DD;
    #pragma unroll
    for (int i = 0; i < 8; i++)
        #pragma unroll
        for (int j = 0; j < 8; j++)
            atomicAdd(&ctx[(t_m + 32 * i) * 64 + t_e + 8 * j], cacc[i][j]);
    if (t_e == 0) {
        #pragma unroll
        for (int i = 0; i < 8; i++)
            atomicAdd(&g_ksum[head * MM + t_m + 32 * i], ksacc[i]);
    }
}

// --------------------------------------------- K4: out = (qp @ ctx) / (qp · ksum)
// dyn smem: ctxs[256*64] qps[16*256] ksums[256] pden[16*17] dinvs[16]
#define K4_SMEM ((256 * 64 + 16 * 256 + 256 + 16 * 17 + 16) * 4)
__global__ void __launch_bounds__(256) k4_out(float* __restrict__ out) {
    extern __shared__ float sm[];
    float* ctxs  = sm;
    float* qps   = ctxs + 256 * 64;
    float* ksums = qps + 16 * 256;
    float* pden  = ksums + 256;
    float* dinvs = pden + 16 * 17;

    int head = blockIdx.y;
    int r_base = blockIdx.x * 512;
    int tid = threadIdx.x;
    for (int i = tid; i < 256 * 64; i += 256) ctxs[i] = g_ctx[(size_t)head * MM * DD + i];
    if (tid < 256) ksums[tid] = g_ksum[head * MM + tid];
    __syncthreads();
    const float* qpb = g_qp + ((size_t)head * NN + r_base) * MM;
    float* ob = out + ((size_t)head * NN + r_base) * DD;
    int e0 = (tid & 31) * 2;
    int rg = tid >> 5;   // 0..7, uniform within warp -> qp broadcast
    for (int ch = 0; ch < 32; ch++) {
        __syncthreads();
        for (int i = tid; i < 16 * 256; i += 256) qps[i] = qpb[(size_t)ch * 16 * 256 + i];
        __syncthreads();
        {   // denominators for 16 rows
            int r = tid >> 4, seg = tid & 15;
            float s = 0.0f;
            for (int m = seg * 16; m < seg * 16 + 16; m++) s += qps[r * 256 + m] * ksums[m];
            pden[r * 17 + seg] = s;
        }
        __syncthreads();
        if (tid < 16) {
            float s = 0.0f;
            #pragma unroll
            for (int j = 0; j < 16; j++) s += pden[tid * 17 + j];
            dinvs[tid] = 1.0f / s;
        }
        __syncthreads();
        #pragma unroll
        for (int ii = 0; ii < 2; ii++) {
            int r = rg + 8 * ii;
            float sx = 0.0f, sy = 0.0f;
            #pragma unroll 8
            for (int m = 0; m < 256; m++) {
                float2 c = *reinterpret_cast<const float2*>(&ctxs[m * 64 + e0]);
                float qv = qps[r * 256 + m];
                sx += qv * c.x;
                sy += qv * c.y;
            }
            float di = dinvs[r];
            float2 o; o.x = sx * di; o.y = sy * di;
            *reinterpret_cast<float2*>(&ob[(size_t)(ch * 16 + r) * 64 + e0]) = o;
        }
    }
}

// ---------------------------------------------------------------- launch
extern "C" void kernel_launch(void* const* d_in, const int* in_sizes, int n_in,
                              void* d_out, int out_size) {
    const float* q = (const float*)d_in[0];
    const float* k = (const float*)d_in[1];
    const float* v = (const float*)d_in[2];
    const float* P = (const float*)d_in[3];
    float* out = (float*)d_out;

    cudaFuncSetAttribute(k2_qp,  cudaFuncAttributeMaxDynamicSharedMemorySize, K2_SMEM);
    cudaFuncSetAttribute(k4_out, cudaFuncAttributeMaxDynamicSharedMemorySize, K4_SMEM);

    int init_tot = NH * MM * DD;
    k0_init<<<(init_tot + 255) / 256, 256>>>();
    k1_kproj<<<dim3(NN / 64, MM / 64, NH), 256>>>(k, P);
    k2_qp<<<dim3(NN / 32, NH), 256, K2_SMEM>>>(q, P);
    k3_ctx<<<dim3(16, NH), 256>>>(v);
    k4_out<<<dim3(8, NH), 256, K4_SMEM>>>(out);
}

// round 3
// speedup vs baseline: 1.4942x; 1.4942x over previous
#include <cuda_runtime.h>
#include <math.h>

#define NH 64      // B*H
#define NN 4096
#define DD 64
#define MM 256

#define SCALE   0.35355339059327379f   // 64^-0.25
#define EPSILON 1e-4f

// ---- scratch (__device__ globals) — 4.3 MB total ----
__device__ float    g_ctxraw [NH * MM * DD];
__device__ float    g_ksumraw[NH * MM];
__device__ float    g_vsum   [NH * DD];
__device__ unsigned g_gmax   [NH];
__device__ float    g_ctxf   [NH * MM * DD];
__device__ float    g_ksumf  [NH * MM];

__device__ __forceinline__ unsigned enc_f(float f) {
    unsigned u = __float_as_uint(f);
    return (u & 0x80000000u) ? ~u : (u | 0x80000000u);
}
__device__ __forceinline__ float dec_f(unsigned u) {
    return __uint_as_float((u & 0x80000000u) ? (u & 0x7fffffffu) : ~u);
}

// FMA-pipe exp: exp(x) = 2^(x*log2e), poly on fractional part. rel err ~1e-7.
__device__ __forceinline__ float fexp(float x) {
    float y = fmaxf(x * 1.4426950408889634f, -126.0f);
    float n = rintf(y);
    float f = y - n;
    float p = 1.5403530393381609e-4f;
    p = fmaf(p, f, 1.3333558146428443e-3f);
    p = fmaf(p, f, 9.6181291076284772e-3f);
    p = fmaf(p, f, 5.5504108664821580e-2f);
    p = fmaf(p, f, 2.4022650695910071e-1f);
    p = fmaf(p, f, 6.9314718055994531e-1f);
    p = fmaf(p, f, 1.0f);
    return p * __int_as_float(((int)n + 127) << 23);
}

// ---------------------------------------------------------------- K0: init
__global__ void k0_init() {
    int i = blockIdx.x * blockDim.x + threadIdx.x;
    if (i < NH * MM * DD) g_ctxraw[i] = 0.0f;
    if (i < NH * MM)      g_ksumraw[i] = 0.0f;
    if (i < NH * DD)      g_vsum[i] = 0.0f;
    if (i < NH)           g_gmax[i] = enc_f(-1e30f);
}

// =============================================================== Kernel A
// Fused k-side: dash = (s*K)·P^T ; w = exp(dash - diag) ;
// ctx_raw += w^T·V ; ksum_raw += Σ_n w ; vsum += Σ_n V ; gmax = max dash
// grid (8, NH), 256 thr, each block: 8 chunks of 64 rows.
#define A_SMEM ((64*256 + 64*68 + 64*256 + 64*68 + 64 + 256) * 4)
__global__ void __launch_bounds__(256, 1) kA(const float* __restrict__ K,
                                             const float* __restrict__ V,
                                             const float* __restrict__ P) {
    extern __shared__ float sm[];
    float* Pt   = sm;                 // [64][256]  P transposed
    float* kp   = Pt + 64 * 256;      // [64][256]  dash -> w
    float* ks   = kp + 64 * 256;      // [64][68]
    float* vs   = ks + 64 * 68;       // [64][68]
    float* diag = vs + 64 * 68;       // [64]
    float* red  = diag + 64;          // [256]

    int tid  = threadIdx.x;
    int head = blockIdx.y;
    int rbase = blockIdx.x * 512;
    const float* kb = K + (size_t)head * NN * DD;
    const float* vb = V + (size_t)head * NN * DD;

    // ---- load P transposed via staged smem transpose (conflict-free) ----
    for (int c = 0; c < 4; c++) {
        for (int i = tid; i < 64 * 64; i += 256) {
            int r = i >> 6, d = i & 63;
            vs[r * 65 + d] = P[(size_t)(c * 64 + r) * 64 + d];
        }
        __syncthreads();
        int m = tid & 63, q4 = tid >> 6;
        for (int d = q4; d < 64; d += 4)
            Pt[d * 256 + c * 64 + m] = vs[m * 65 + d];
        __syncthreads();
    }

    int t_e = tid & 7, t_m = tid >> 3;
    int ty = tid >> 5, tx = tid & 31;
    float cacc[8][8] = {};
    float ksacc[8] = {};
    float vsacc = 0.0f;
    float lmax = -1e30f;

    for (int ch = 0; ch < 8; ch++) {
        int n0 = rbase + ch * 64;
        __syncthreads();
        for (int i = tid; i < 64 * 64; i += 256) {
            int r = i >> 6, d = i & 63;
            ks[r * 68 + d] = SCALE * kb[(size_t)(n0 + r) * 64 + d];
            vs[r * 68 + d] = vb[(size_t)(n0 + r) * 64 + d];
        }
        __syncthreads();
        if (tid < 64) {
            float s = 0.0f;
            #pragma unroll 8
            for (int d = 0; d < 64; d++) { float t = ks[tid * 68 + d]; s += t * t; }
            diag[tid] = 0.5f * s;
        } else if (tid < 128) {
            int e = tid - 64;
            float s = 0.0f;
            #pragma unroll 8
            for (int r = 0; r < 64; r++) s += vs[r * 68 + e];
            vsacc += s;
        }
        // ---- dash GEMM: kp[64][256] = ks(64x64) · Pt(64x256) ----
        {
            float dacc[8][8] = {};
            #pragma unroll 8
            for (int d = 0; d < 64; d++) {
                float a[8], b[8];
                #pragma unroll
                for (int i = 0; i < 8; i++) a[i] = ks[(ty + 8 * i) * 68 + d];
                #pragma unroll
                for (int j = 0; j < 8; j++) b[j] = Pt[d * 256 + tx + 32 * j];
                #pragma unroll
                for (int i = 0; i < 8; i++)
                    #pragma unroll
                    for (int j = 0; j < 8; j++) dacc[i][j] += a[i] * b[j];
            }
            #pragma unroll
            for (int i = 0; i < 8; i++)
                #pragma unroll
                for (int j = 0; j < 8; j++) {
                    float v = dacc[i][j];
                    lmax = fmaxf(lmax, v);
                    kp[(ty + 8 * i) * 256 + tx + 32 * j] = v;
                }
        }
        __syncthreads();
        // ---- exp (FMA-pipe): w = exp(dash - diag) ----
        #pragma unroll 8
        for (int r = 0; r < 64; r++) {
            int idx = r * 256 + tid;
            kp[idx] = fexp(kp[idx] - diag[r]);
        }
        __syncthreads();
        // ---- ctx GEMM: cacc[m,e] += w^T · V, ksacc += column sums of w ----
        #pragma unroll 4
        for (int nn = 0; nn < 64; nn++) {
            float a[8], b[8];
            #pragma unroll
            for (int i = 0; i < 8; i++) a[i] = kp[nn * 256 + t_m + 32 * i];
            #pragma unroll
            for (int j = 0; j < 8; j++) b[j] = vs[nn * 68 + t_e + 8 * j];
            #pragma unroll
            for (int i = 0; i < 8; i++)
                #pragma unroll
                for (int j = 0; j < 8; j++) cacc[i][j] += a[i] * b[j];
            if (t_e == 0) {
                #pragma unroll
                for (int i = 0; i < 8; i++) ksacc[i] += a[i];
            }
        }
    }

    float* ctx = g_ctxraw + (size_t)head * MM * DD;
    #pragma unroll
    for (int i = 0; i < 8; i++)
        #pragma unroll
        for (int j = 0; j < 8; j++)
            atomicAdd(&ctx[(t_m + 32 * i) * 64 + t_e + 8 * j], cacc[i][j]);
    if (t_e == 0) {
        #pragma unroll
        for (int i = 0; i < 8; i++)
            atomicAdd(&g_ksumraw[head * MM + t_m + 32 * i], ksacc[i]);
    }
    if (tid >= 64 && tid < 128) atomicAdd(&g_vsum[head * DD + tid - 64], vsacc);

    red[tid] = lmax;
    __syncthreads();
    for (int s = 128; s > 0; s >>= 1) {
        if (tid < s) red[tid] = fmaxf(red[tid], red[tid + s]);
        __syncthreads();
    }
    if (tid == 0) atomicMax(&g_gmax[head], enc_f(red[0]));
}

// =============================================================== Kernel B
// Finalize: ctxf = e^{-gmax}·ctx_raw + eps·vsum ; ksumf = e^{-gmax}·ksum_raw + eps·N
__global__ void kB() {
    int head = blockIdx.x;
    int tid = threadIdx.x;
    float emx = fexp(-dec_f(g_gmax[head]));
    g_ksumf[head * MM + tid] = emx * g_ksumraw[head * MM + tid] + EPSILON * (float)NN;
    size_t base = (size_t)head * MM * DD;
    for (int i = tid; i < MM * DD; i += 256) {
        int e = i & 63;
        g_ctxf[base + i] = emx * g_ctxraw[base + i] + EPSILON * g_vsum[head * DD + e];
    }
}

// =============================================================== Kernel C
// Fused q-side: dash = (s*Q)·P^T ; w = exp(dash - diag - rowmax) + eps ;
// out = (w · ctxf) / (w · ksumf)        (ratio factors cancel)
// grid (8, NH), 256 thr, each block: 8 chunks of 64 rows.
#define C_SMEM ((64*256 + 256*64 + 64*256 + 64*68 + 256 + 64 + 64 + 256 + 256 + 64) * 4)
__global__ void __launch_bounds__(256, 1) kC(const float* __restrict__ Q,
                                             const float* __restrict__ P,
                                             float* __restrict__ out) {
    extern __shared__ float sm[];
    float* Pt   = sm;                  // [64][256]
    float* ctxs = Pt + 64 * 256;       // [256][64]
    float* dash = ctxs + 256 * 64;     // [64][256] -> w
    float* qs   = dash + 64 * 256;     // [64][68]
    float* ksums= qs + 64 * 68;        // [256]
    float* diag = ksums + 256;         // [64]
    float* mxs  = diag + 64;           // [64]
    float* pm   = mxs + 64;            // [64][4]
    float* pden = pm + 256;            // [64][4]
    float* dinv = pden + 256;          // [64]

    int tid  = threadIdx.x;
    int head = blockIdx.y;
    int rbase = blockIdx.x * 512;
    const float* qb = Q + (size_t)head * NN * DD;

    // persistent loads: P transposed (staged via qs), ctxf, ksumf
    for (int c = 0; c < 4; c++) {
        for (int i = tid; i < 64 * 64; i += 256) {
            int r = i >> 6, d = i & 63;
            qs[r * 65 + d] = P[(size_t)(c * 64 + r) * 64 + d];
        }
        __syncthreads();
        int m = tid & 63, q4 = tid >> 6;
        for (int d = q4; d < 64; d += 4)
            Pt[d * 256 + c * 64 + m] = qs[m * 65 + d];
        __syncthreads();
    }
    for (int i = tid; i < 256 * 64; i += 256) ctxs[i] = g_ctxf[(size_t)head * MM * DD + i];
    ksums[tid] = g_ksumf[head * MM + tid];

    int ty = tid >> 5, tx = tid & 31;       // dash GEMM layout
    int oy = tid >> 4, ox = tid & 15;       // out GEMM layout (4x4 micro, float4)

    for (int ch = 0; ch < 8; ch++) {
        int n0 = rbase + ch * 64;
        __syncthreads();
        for (int i = tid; i < 64 * 64; i += 256) {
            int r = i >> 6, d = i & 63;
            qs[r * 68 + d] = SCALE * qb[(size_t)(n0 + r) * 64 + d];
        }
        __syncthreads();
        if (tid < 64) {
            float s = 0.0f;
            #pragma unroll 8
            for (int d = 0; d < 64; d++) { float t = qs[tid * 68 + d]; s += t * t; }
            diag[tid] = 0.5f * s;
        }
        // ---- dash GEMM: dash[64][256] = qs(64x64) · Pt(64x256) ----
        {
            float dacc[8][8] = {};
            #pragma unroll 8
            for (int d = 0; d < 64; d++) {
                float a[8], b[8];
                #pragma unroll
                for (int i = 0; i < 8; i++) a[i] = qs[(ty + 8 * i) * 68 + d];
                #pragma unroll
                for (int j = 0; j < 8; j++) b[j] = Pt[d * 256 + tx + 32 * j];
                #pragma unroll
                for (int i = 0; i < 8; i++)
                    #pragma unroll
                    for (int j = 0; j < 8; j++) dacc[i][j] += a[i] * b[j];
            }
            #pragma unroll
            for (int i = 0; i < 8; i++)
                #pragma unroll
                for (int j = 0; j < 8; j++)
                    dash[(ty + 8 * i) * 256 + tx + 32 * j] = dacc[i][j];
        }
        __syncthreads();
        // ---- row max over 256 features ----
        {
            int r = tid >> 2, seg = tid & 3;
            float m = -1e30f;
            #pragma unroll 8
            for (int mm = seg * 64; mm < seg * 64 + 64; mm++) m = fmaxf(m, dash[r * 256 + mm]);
            pm[r * 4 + seg] = m;
        }
        __syncthreads();
        if (tid < 64)
            mxs[tid] = fmaxf(fmaxf(pm[tid * 4], pm[tid * 4 + 1]),
                             fmaxf(pm[tid * 4 + 2], pm[tid * 4 + 3]));
        __syncthreads();
        // ---- w = exp(dash - diag - rowmax) + eps (in place) ----
        #pragma unroll 8
        for (int r = 0; r < 64; r++) {
            int idx = r * 256 + tid;
            dash[idx] = fexp(dash[idx] - diag[r] - mxs[r]) + EPSILON;
        }
        __syncthreads();
        // ---- denominators: den[r] = Σ_m w·ksumf ----
        {
            int r = tid >> 2, seg = tid & 3;
            float s = 0.0f;
            #pragma unroll 8
            for (int mm = seg * 64; mm < seg * 64 + 64; mm++)
                s += dash[r * 256 + mm] * ksums[mm];
            pden[r * 4 + seg] = s;
        }
        __syncthreads();
        if (tid < 64)
            dinv[tid] = 1.0f / (pden[tid * 4] + pden[tid * 4 + 1] +
                                pden[tid * 4 + 2] + pden[tid * 4 + 3]);
        __syncthreads();
        // ---- out GEMM: out[64][64] = w(64x256) · ctxs(256x64), float4 duals ----
        {
            float oacc[4][4] = {};
            #pragma unroll 4
            for (int m = 0; m < 256; m += 4) {
                float4 a[4], b[4];
                #pragma unroll
                for (int i = 0; i < 4; i++)
                    a[i] = *reinterpret_cast<const float4*>(&dash[(oy * 4 + i) * 256 + m]);
                #pragma unroll
                for (int mm = 0; mm < 4; mm++)
                    b[mm] = *reinterpret_cast<const float4*>(&ctxs[(m + mm) * 64 + ox * 4]);
                #pragma unroll
                for (int i = 0; i < 4; i++) {
                    oacc[i][0] += a[i].x * b[0].x; oacc[i][1] += a[i].x * b[0].y;
                    oacc[i][2] += a[i].x * b[0].z; oacc[i][3] += a[i].x * b[0].w;
                    oacc[i][0] += a[i].y * b[1].x; oacc[i][1] += a[i].y * b[1].y;
                    oacc[i][2] += a[i].y * b[1].z; oacc[i][3] += a[i].y * b[1].w;
                    oacc[i][0] += a[i].z * b[2].x; oacc[i][1] += a[i].z * b[2].y;
                    oacc[i][2] += a[i].z * b[2].z; oacc[i][3] += a[i].z * b[2].w;
                    oacc[i][0] += a[i].w * b[3].x; oacc[i][1] += a[i].w * b[3].y;
                    oacc[i][2] += a[i].w * b[3].z; oacc[i][3] += a[i].w * b[3].w;
                }
            }
            float* ob = out + ((size_t)head * NN + n0) * DD;
            #pragma unroll
            for (int i = 0; i < 4; i++) {
                int r = oy * 4 + i;
                float di = dinv[r];
                float4 o;
                o.x = oacc[i][0] * di; o.y = oacc[i][1] * di;
                o.z = oacc[i][2] * di; o.w = oacc[i][3] * di;
                *reinterpret_cast<float4*>(&ob[(size_t)r * 64 + ox * 4]) = o;
            }
        }
    }
}

// ---------------------------------------------------------------- launch
extern "C" void kernel_launch(void* const* d_in, const int* in_sizes, int n_in,
                              void* d_out, int out_size) {
    const float* q = (const float*)d_in[0];
    const float* k = (const float*)d_in[1];
    const float* v = (const float*)d_in[2];
    const float* P = (const float*)d_in[3];
    float* out = (float*)d_out;

    cudaFuncSetAttribute(kA, cudaFuncAttributeMaxDynamicSharedMemorySize, A_SMEM);
    cudaFuncSetAttribute(kC, cudaFuncAttributeMaxDynamicSharedMemorySize, C_SMEM);

    k0_init<<<(NH * MM * DD + 255) / 256, 256>>>();
    kA<<<dim3(8, NH), 256, A_SMEM>>>(k, v, P);
    kB<<<NH, 256>>>();
    kC<<<dim3(8, NH), 256, C_SMEM>>>(q, P, out);
}